// round 6
// baseline (speedup 1.0000x reference)
#include <cuda_runtime.h>
#include <math.h>

// Problem dims
#define BB   128
#define NN   32
#define OBSD 128
#define AD   16
#define HH   4
#define DMD  128
#define ED   32
#define OAD  144
#define F1D  64
#define FIND 16
#define V0   (BB*NN*NN*FIND)   // weights start offset in d_out (value first, weights second)

// Scratch (device globals — no allocation allowed)
__device__ float g_aproj[BB*HH*NN*F1D];   // av_act @ W_f1_h
__device__ float g_dproj[BB*HH*NN*F1D];   // (av_pol-av_act) @ W_f1_h
__device__ float g_M [HH*DMD*DMD];        // (W_q W_k^T) / sqrt(DM) per head
__device__ float g_v2[HH*DMD];            // (W_k b_q) / sqrt(DM) per head

__device__ __forceinline__ float lrelu(float x) { return x > 0.f ? x : 0.01f * x; }

#define INV_SQRT_DM 0.08838834764831845f

// ---------------------------------------------------------------------------
// k0: M_h = (W_q W_k^T)/sqrt(DM), v2_h = (W_k b_q)/sqrt(DM).
// grid = 256: h = bx>>6; rt = (bx>>2)&15 (8 d-rows); ct = bx&3 (32 d'-cols).
// Warp w -> row rt*8+w; lane -> col ct*32+lane. One output/thread,
// 4 independent accumulation chains. B tile in smem (conflict-free),
// A rows via warp-uniform __ldg float4 (L1/L2 broadcast, shared across blocks).
// ---------------------------------------------------------------------------
#define K0_SMEM_F (128 * 33)

__global__ __launch_bounds__(256)
void k0_prep(const float* __restrict__ W_q, const float* __restrict__ W_k,
             const float* __restrict__ b_q)
{
    const int h  = blockIdx.x >> 6;
    const int rt = (blockIdx.x >> 2) & 15;
    const int ct = blockIdx.x & 3;
    extern __shared__ float sm[];
    float* BT = sm;   // [128][33]: BT[e][dl] = W_k[h][ct*32+dl][e]
    const int tid  = threadIdx.x;
    const int w    = tid >> 5;
    const int lane = tid & 31;

    {
        const float* src = W_k + (size_t)h * DMD * DMD + (size_t)ct * 32 * DMD;
        for (int i = tid; i < 32 * DMD; i += 256) {
            int dl = i >> 7, e = i & 127;
            BT[e * 33 + dl] = src[i];
        }
    }
    __syncthreads();

    const int d = rt * 8 + w;
    const float4* Arow = (const float4*)(W_q + (size_t)h * DMD * DMD + (size_t)d * DMD);

    float a0 = 0.f, a1 = 0.f, a2 = 0.f, a3 = 0.f;
    #pragma unroll 8
    for (int e4 = 0; e4 < 32; e4++) {
        float4 a = __ldg(Arow + e4);                 // warp-uniform broadcast
        int eb = e4 * 4;
        a0 += a.x * BT[(eb + 0) * 33 + lane];
        a1 += a.y * BT[(eb + 1) * 33 + lane];
        a2 += a.z * BT[(eb + 2) * 33 + lane];
        a3 += a.w * BT[(eb + 3) * 33 + lane];
    }
    g_M[(size_t)h * DMD * DMD + (size_t)d * DMD + ct * 32 + lane] =
        ((a0 + a1) + (a2 + a3)) * INV_SQRT_DM;

    if (rt == 0 && w == 0) {
        const float* bq = b_q + h * DMD;
        float s0 = 0.f, s1 = 0.f, s2 = 0.f, s3 = 0.f;
        #pragma unroll 8
        for (int e = 0; e < DMD; e += 4) {
            s0 += BT[(e + 0) * 33 + lane] * __ldg(bq + e + 0);
            s1 += BT[(e + 1) * 33 + lane] * __ldg(bq + e + 1);
            s2 += BT[(e + 2) * 33 + lane] * __ldg(bq + e + 2);
            s3 += BT[(e + 3) * 33 + lane] * __ldg(bq + e + 3);
        }
        g_v2[h * DMD + ct * 32 + lane] = ((s0 + s1) + (s2 + s3)) * INV_SQRT_DM;
    }
}

// ---------------------------------------------------------------------------
// k12: merged attention (role 0) + state-action-pair (role 1) kernel.
// (Round-4 measured-good configuration: 3 CTAs/SM, no buffer aliasing in role0)
// ---------------------------------------------------------------------------
#define K12_SMEM_F (18720)

__global__ __launch_bounds__(256, 3)
void k12(const float* __restrict__ states,
         const float* __restrict__ policies,
         const float* __restrict__ actions,
         const float* __restrict__ W_se, const float* __restrict__ b_se,
         const float* __restrict__ W_sap, const float* __restrict__ b_sap,
         const float* __restrict__ W_av,  const float* __restrict__ b_av,
         const float* __restrict__ W_f1,
         float* __restrict__ out_w)
{
    extern __shared__ float sm[];
    const int tid  = threadIdx.x;
    const int role = blockIdx.x & 1;
    const int idx  = blockIdx.x >> 1;       // 0..511
    const int h    = idx & 3;
    const int b    = idx >> 2;

    if (role == 0) {
        // ================= attention weights =================
        float* sT  = sm;            // [128][36]  states o-major
        float* seT = sm + 4608;     // [128][36]  se d-major
        float* seR = sm + 9216;     // [32][132]  se row-major
        float* tb  = sm + 13440;    // [32][132]  t = se@M row-major
        float* sc  = sm + 17664;    // [32][32]
        float* rv  = sm + 18688;    // [32]

        const float* sb = states + b * NN * OBSD;
        for (int i = tid; i < NN * OBSD; i += 256) {
            int n = i >> 7, o = i & 127;
            sT[o * 36 + n] = sb[i];
        }
        __syncthreads();

        const int tr = tid >> 5;   // rows 4*tr
        const int tc = tid & 31;   // cols 4*tc

        // ---- se = leaky(states @ W_se + b_se) -> seT (d-major) + seR (row) ----
        {
            const float* Wh = W_se + (size_t)h * OBSD * DMD;
            float acc[4][4];
            #pragma unroll
            for (int r = 0; r < 4; r++)
                #pragma unroll
                for (int c = 0; c < 4; c++) acc[r][c] = 0.f;
            #pragma unroll 4
            for (int o = 0; o < OBSD; o++) {
                float4 a = *(const float4*)(sT + o * 36 + 4 * tr);
                float4 w = __ldg((const float4*)(Wh + o * DMD + 4 * tc));
                float av[4] = {a.x, a.y, a.z, a.w};
                float wv[4] = {w.x, w.y, w.z, w.w};
                #pragma unroll
                for (int r = 0; r < 4; r++)
                    #pragma unroll
                    for (int c = 0; c < 4; c++) acc[r][c] += av[r] * wv[c];
            }
            float4 bs = __ldg((const float4*)(b_se + h * DMD + 4 * tc));
            float bb4[4] = {bs.x, bs.y, bs.z, bs.w};
            #pragma unroll
            for (int c = 0; c < 4; c++) {
                int d = 4 * tc + c;
                #pragma unroll
                for (int r = 0; r < 4; r++) {
                    float v = lrelu(acc[r][c] + bb4[c]);
                    seT[d * 36 + 4 * tr + r] = v;
                    seR[(4 * tr + r) * 132 + d] = v;
                }
            }
        }
        __syncthreads();

        // ---- t = se @ M_h (pre-scaled) ----
        {
            const float* Mh = g_M + (size_t)h * DMD * DMD;
            float acc[4][4];
            #pragma unroll
            for (int r = 0; r < 4; r++)
                #pragma unroll
                for (int c = 0; c < 4; c++) acc[r][c] = 0.f;
            #pragma unroll 4
            for (int d = 0; d < DMD; d++) {
                float4 a = *(const float4*)(seT + d * 36 + 4 * tr);
                float4 w = __ldg((const float4*)(Mh + (size_t)d * DMD + 4 * tc));
                float av[4] = {a.x, a.y, a.z, a.w};
                float wv[4] = {w.x, w.y, w.z, w.w};
                #pragma unroll
                for (int r = 0; r < 4; r++)
                    #pragma unroll
                    for (int c = 0; c < 4; c++) acc[r][c] += av[r] * wv[c];
            }
            #pragma unroll
            for (int r = 0; r < 4; r++)
                *(float4*)(tb + (4 * tr + r) * 132 + 4 * tc) =
                    make_float4(acc[r][0], acc[r][1], acc[r][2], acc[r][3]);
        }
        // ---- rv[j] = v2 . se_j (threads 0..127) ----
        if (tid < 128) {
            const int j = tid >> 2, part = tid & 3;
            const float* v2 = g_v2 + h * DMD;
            float s = 0.f;
            #pragma unroll 8
            for (int e = part * 32; e < part * 32 + 32; e++)
                s += v2[e] * seR[j * 132 + e];
            s += __shfl_xor_sync(0xffffffffu, s, 1);
            s += __shfl_xor_sync(0xffffffffu, s, 2);
            if (part == 0) rv[j] = s;
        }
        __syncthreads();

        // ---- scores_ij = t_i . se_j + rv_j (already scaled) ----
        {
            const int i  = tid >> 3;
            const int j0 = (tid & 7) * 4;
            float s4[4] = {0.f, 0.f, 0.f, 0.f};
            #pragma unroll 4
            for (int e = 0; e < DMD; e += 4) {
                float4 qv = *(const float4*)(tb + i * 132 + e);
                #pragma unroll
                for (int jj = 0; jj < 4; jj++) {
                    float4 kv = *(const float4*)(seR + (j0 + jj) * 132 + e);
                    s4[jj] += qv.x * kv.x + qv.y * kv.y + qv.z * kv.z + qv.w * kv.w;
                }
            }
            #pragma unroll
            for (int jj = 0; jj < 4; jj++)
                sc[i * 32 + j0 + jj] = s4[jj] + rv[j0 + jj];
        }
        __syncthreads();

        // ---- softmax over j -> d_out tail ----
        {
            const int lane = tid & 31, wp = tid >> 5;
            float* dst = out_w + ((size_t)(b * HH + h) * NN) * NN;
            #pragma unroll
            for (int rr = 0; rr < 4; rr++) {
                int i = wp * 4 + rr;
                float v = sc[i * 32 + lane];
                float m = v;
                #pragma unroll
                for (int off = 16; off > 0; off >>= 1)
                    m = fmaxf(m, __shfl_xor_sync(0xffffffffu, m, off));
                float e = __expf(v - m);
                float s = e;
                #pragma unroll
                for (int off = 16; off > 0; off >>= 1)
                    s += __shfl_xor_sync(0xffffffffu, s, off);
                dst[i * NN + lane] = e / s;
            }
        }
    } else {
        // ================= sap embeddings -> Aproj/Dproj =================
        float* sT   = sm;            // [128][36]
        float* aT   = sm + 4608;     // [16][36]
        float* pT   = sm + 5184;     // [16][36]
        float* embT = sm + 5760;     // [128][68] cols 0..31 act, 32..63 pol
        float* avs  = sm;            // [64][36]  (aliases sT after emb phase)
        float* wf1h = sm + 5760;     // [32][64]  (aliases embT after av phase)

        const float* sb = states + b * NN * OBSD;
        for (int i = tid; i < NN * OBSD; i += 256) {
            int n = i >> 7, o = i & 127;
            sT[o * 36 + n] = sb[i];
        }
        const float* ab = actions  + b * NN * AD;
        const float* pb = policies + b * NN * AD;
        for (int i = tid; i < NN * AD; i += 256) {
            int n = i >> 4, c = i & 15;
            aT[c * 36 + n] = ab[i];
            pT[c * 36 + n] = pb[i];
        }
        __syncthreads();

        const int tr = tid >> 5;  // rows 4*tr of 32
        const int tc = tid & 31;  // cols 4*tc of 128

        // ---- sp = states @ W_sap[0:128]; emb = leaky(sp + tail + b) ----
        {
            const float* Wh = W_sap + (size_t)h * OAD * DMD;
            float acc[4][4];
            #pragma unroll
            for (int r = 0; r < 4; r++)
                #pragma unroll
                for (int c = 0; c < 4; c++) acc[r][c] = 0.f;
            #pragma unroll 4
            for (int o = 0; o < OBSD; o++) {
                float4 a = *(const float4*)(sT + o * 36 + 4 * tr);
                float4 w = __ldg((const float4*)(Wh + o * DMD + 4 * tc));
                float av[4] = {a.x, a.y, a.z, a.w};
                float wv[4] = {w.x, w.y, w.z, w.w};
                #pragma unroll
                for (int r = 0; r < 4; r++)
                    #pragma unroll
                    for (int c = 0; c < 4; c++) acc[r][c] += av[r] * wv[c];
            }
            float4 bs = __ldg((const float4*)(b_sap + h * DMD + 4 * tc));
            float bb4[4] = {bs.x, bs.y, bs.z, bs.w};

            // action tail + store
            {
                float accA[4][4];
                #pragma unroll
                for (int r = 0; r < 4; r++)
                    #pragma unroll
                    for (int c = 0; c < 4; c++) accA[r][c] = acc[r][c];
                #pragma unroll 4
                for (int c16 = 0; c16 < AD; c16++) {
                    float4 a = *(const float4*)(aT + c16 * 36 + 4 * tr);
                    float4 w = __ldg((const float4*)(Wh + (size_t)(OBSD + c16) * DMD + 4 * tc));
                    float av[4] = {a.x, a.y, a.z, a.w};
                    float wv[4] = {w.x, w.y, w.z, w.w};
                    #pragma unroll
                    for (int r = 0; r < 4; r++)
                        #pragma unroll
                        for (int c = 0; c < 4; c++) accA[r][c] += av[r] * wv[c];
                }
                #pragma unroll
                for (int c = 0; c < 4; c++) {
                    int d = 4 * tc + c;
                    #pragma unroll
                    for (int r = 0; r < 4; r++)
                        embT[d * 68 + 4 * tr + r] = lrelu(accA[r][c] + bb4[c]);
                }
            }
            // policy tail + store (reuses acc in place; acc dead after)
            {
                #pragma unroll 4
                for (int c16 = 0; c16 < AD; c16++) {
                    float4 a = *(const float4*)(pT + c16 * 36 + 4 * tr);
                    float4 w = __ldg((const float4*)(Wh + (size_t)(OBSD + c16) * DMD + 4 * tc));
                    float av[4] = {a.x, a.y, a.z, a.w};
                    float wv[4] = {w.x, w.y, w.z, w.w};
                    #pragma unroll
                    for (int r = 0; r < 4; r++)
                        #pragma unroll
                        for (int c = 0; c < 4; c++) acc[r][c] += av[r] * wv[c];
                }
                #pragma unroll
                for (int c = 0; c < 4; c++) {
                    int d = 4 * tc + c;
                    #pragma unroll
                    for (int r = 0; r < 4; r++)
                        embT[d * 68 + 32 + 4 * tr + r] = lrelu(acc[r][c] + bb4[c]);
                }
            }
        }
        __syncthreads();

        // ---- av (64 x 32) -> avs (aliases sT/aT/pT region; dead now) ----
        {
            const int tr2 = tid >> 4;  // 0..15 -> rows 4*tr2 of 64
            const int tc2 = tid & 15;  // 0..15 -> cols 2*tc2 of 32
            const float* Wh = W_av + (size_t)h * DMD * ED;
            float acc[4][2];
            #pragma unroll
            for (int r = 0; r < 4; r++) { acc[r][0] = 0.f; acc[r][1] = 0.f; }
            #pragma unroll 4
            for (int d = 0; d < DMD; d++) {
                float4 a = *(const float4*)(embT + d * 68 + 4 * tr2);
                float2 w = __ldg((const float2*)(Wh + d * ED + 2 * tc2));
                float av[4] = {a.x, a.y, a.z, a.w};
                #pragma unroll
                for (int r = 0; r < 4; r++) {
                    acc[r][0] += av[r] * w.x;
                    acc[r][1] += av[r] * w.y;
                }
            }
            float2 bv = __ldg((const float2*)(b_av + h * ED + 2 * tc2));
            #pragma unroll
            for (int r = 0; r < 4; r++) {
                int m = 4 * tr2 + r;
                avs[m * 36 + 2 * tc2]     = lrelu(acc[r][0] + bv.x);
                avs[m * 36 + 2 * tc2 + 1] = lrelu(acc[r][1] + bv.y);
            }
        }
        __syncthreads();   // embT reads done -> safe to overwrite with wf1h

        {
            const float4* src = (const float4*)(W_f1 + (size_t)h * ED * F1D);
            float4* dst = (float4*)wf1h;
            for (int i = tid; i < ED * F1D / 4; i += 256) dst[i] = src[i];
        }
        __syncthreads();

        // ---- Aproj / Dproj: [32][64] each ----
        {
            const int u  = tid & 63;
            const int i0 = tid >> 6;
            #pragma unroll
            for (int r = 0; r < 8; r++) {
                int j = i0 * 8 + r;
                float pa = 0.f, pd = 0.f;
                #pragma unroll 4
                for (int e = 0; e < ED; e++) {
                    float aa = avs[j * 36 + e];
                    float dd = avs[(32 + j) * 36 + e] - aa;
                    float wv = wf1h[e * F1D + u];
                    pa += aa * wv;
                    pd += dd * wv;
                }
                size_t o = ((size_t)(b * HH + h) * NN + j) * F1D + u;
                g_aproj[o] = pa;
                g_dproj[o] = pd;
            }
        }
    }
}

// ---------------------------------------------------------------------------
// K3: grid = 2*B; block (b, half) handles i-rows [half*16, half*16+16).
// ---------------------------------------------------------------------------
#define K3_SMEM_F (2048 + 8192 + 8448 + 1024 + 1024 + 64 + 16)

__global__ __launch_bounds__(256, 2)
void k3_final(const float* __restrict__ b_f1,
              const float* __restrict__ W_f2, const float* __restrict__ b_f2,
              const float* __restrict__ wgt,  // d_out + V0
              float* __restrict__ val)        // d_out
{
    const int half   = blockIdx.x & 1;
    const int b      = blockIdx.x >> 1;
    const int base_i = half * 16;
    extern __shared__ float sm[];
    float* w4h   = sm;           // [4][16][32]
    float* aproj = sm + 2048;    // [4][32][64]
    float* dpT   = sm + 10240;   // [4][64][33]
    float* P     = sm + 18688;   // [16][64]
    float* wf2   = sm + 19712;   // [64][16]
    float* bf1   = sm + 20736;   // [64]
    float* bf2   = sm + 20800;   // [16]
    const int tid = threadIdx.x;

    {
        const float* wg = wgt + (size_t)b * 4096;
        for (int i = tid; i < 2048 / 4; i += 256) {
            int e4 = i * 4;
            int hh = e4 >> 9, rem = e4 & 511;
            int il = rem >> 5, k = rem & 31;
            *(float4*)(w4h + e4) =
                *(const float4*)(wg + ((size_t)hh * 32 + base_i + il) * 32 + k);
        }
    }
    {
        const float4* src = (const float4*)(g_aproj + (size_t)b * 8192);
        float4* dst = (float4*)aproj;
        for (int i = tid; i < 2048; i += 256) dst[i] = src[i];
    }
    {
        const float* dp = g_dproj + (size_t)b * 8192;
        for (int i = tid; i < 8192; i += 256) {
            int hh = i >> 11, j = (i >> 6) & 31, u = i & 63;
            dpT[(hh * 64 + u) * 33 + j] = dp[i];
        }
    }
    for (int i = tid; i < 1024; i += 256) wf2[i] = W_f2[i];
    if (tid < 64) bf1[tid] = b_f1[tid];
    if (tid < 16) bf2[tid] = b_f2[tid];
    __syncthreads();

    // ---- P[il][u] ----
    {
        const int u  = tid & 63;
        const int i0 = tid >> 6;
        float pacc[4];
        #pragma unroll
        for (int r = 0; r < 4; r++) pacc[r] = bf1[u];
        #pragma unroll 2
        for (int hk = 0; hk < 128; hk++) {
            int hh = hk >> 5, k = hk & 31;
            float av = aproj[(hh * 32 + k) * 64 + u];
            #pragma unroll
            for (int r = 0; r < 4; r++)
                pacc[r] += w4h[hh * 512 + (i0 * 4 + r) * 32 + k] * av;
        }
        #pragma unroll
        for (int r = 0; r < 4; r++) P[(i0 * 4 + r) * 64 + u] = pacc[r];
    }
    __syncthreads();

    // ---- fused per-(i,j) MLP ----
    #pragma unroll
    for (int it = 0; it < 2; it++) {
        const int p  = tid + 256 * it;
        const int il = p >> 5;
        const int j  = p & 31;
        float wr0 = w4h[0 * 512 + il * 32 + j];
        float wr1 = w4h[1 * 512 + il * 32 + j];
        float wr2 = w4h[2 * 512 + il * 32 + j];
        float wr3 = w4h[3 * 512 + il * 32 + j];
        float o[16];
        #pragma unroll
        for (int f = 0; f < 16; f++) o[f] = bf2[f];
        #pragma unroll 8
        for (int u = 0; u < 64; u++) {
            float t = P[il * 64 + u];
            t += wr0 * dpT[(0 * 64 + u) * 33 + j];
            t += wr1 * dpT[(1 * 64 + u) * 33 + j];
            t += wr2 * dpT[(2 * 64 + u) * 33 + j];
            t += wr3 * dpT[(3 * 64 + u) * 33 + j];
            float hv = lrelu(t);
            float4 a  = *(const float4*)(wf2 + u * 16 + 0);
            float4 c4 = *(const float4*)(wf2 + u * 16 + 4);
            float4 c8 = *(const float4*)(wf2 + u * 16 + 8);
            float4 cc = *(const float4*)(wf2 + u * 16 + 12);
            o[0]  += hv * a.x;  o[1]  += hv * a.y;  o[2]  += hv * a.z;  o[3]  += hv * a.w;
            o[4]  += hv * c4.x; o[5]  += hv * c4.y; o[6]  += hv * c4.z; o[7]  += hv * c4.w;
            o[8]  += hv * c8.x; o[9]  += hv * c8.y; o[10] += hv * c8.z; o[11] += hv * c8.w;
            o[12] += hv * cc.x; o[13] += hv * cc.y; o[14] += hv * cc.z; o[15] += hv * cc.w;
        }
        float* dst = val + (((size_t)b * NN + base_i + il) * NN + j) * FIND;
        *(float4*)(dst + 0)  = make_float4(o[0],  o[1],  o[2],  o[3]);
        *(float4*)(dst + 4)  = make_float4(o[4],  o[5],  o[6],  o[7]);
        *(float4*)(dst + 8)  = make_float4(o[8],  o[9],  o[10], o[11]);
        *(float4*)(dst + 12) = make_float4(o[12], o[13], o[14], o[15]);
    }
}

// ---------------------------------------------------------------------------
extern "C" void kernel_launch(void* const* d_in, const int* in_sizes, int n_in,
                              void* d_out, int out_size)
{
    (void)in_sizes; (void)n_in; (void)out_size;
    const float* states   = (const float*)d_in[0];
    const float* policies = (const float*)d_in[1];
    const float* actions  = (const float*)d_in[2];
    const float* W_se  = (const float*)d_in[3];  const float* b_se = (const float*)d_in[4];
    const float* W_k   = (const float*)d_in[5];  const float* b_k  = (const float*)d_in[6];
    const float* W_q   = (const float*)d_in[7];  const float* b_q  = (const float*)d_in[8];
    const float* W_sap = (const float*)d_in[9];  const float* b_sap= (const float*)d_in[10];
    const float* W_av  = (const float*)d_in[11]; const float* b_av = (const float*)d_in[12];
    const float* W_f1  = (const float*)d_in[13]; const float* b_f1 = (const float*)d_in[14];
    const float* W_f2  = (const float*)d_in[15]; const float* b_f2 = (const float*)d_in[16];
    (void)b_k;
    float* out   = (float*)d_out;
    float* out_w = out + V0;

    cudaFuncSetAttribute(k0_prep,  cudaFuncAttributeMaxDynamicSharedMemorySize, K0_SMEM_F * 4);
    cudaFuncSetAttribute(k12,      cudaFuncAttributeMaxDynamicSharedMemorySize, K12_SMEM_F * 4);
    cudaFuncSetAttribute(k3_final, cudaFuncAttributeMaxDynamicSharedMemorySize, K3_SMEM_F * 4);

    k0_prep<<<256, 256, K0_SMEM_F * 4>>>(W_q, W_k, b_q);
    k12<<<BB * HH * 2, 256, K12_SMEM_F * 4>>>(states, policies, actions,
                                              W_se, b_se,
                                              W_sap, b_sap, W_av, b_av, W_f1, out_w);
    k3_final<<<BB * 2, 256, K3_SMEM_F * 4>>>(b_f1, W_f2, b_f2, out_w, out);
}

// round 7
// speedup vs baseline: 1.6025x; 1.6025x over previous
#include <cuda_runtime.h>
#include <math.h>

// Problem dims
#define BB   128
#define NN   32
#define OBSD 128
#define AD   16
#define HH   4
#define DMD  128
#define ED   32
#define OAD  144
#define F1D  64
#define FIND 16
#define V0   (BB*NN*NN*FIND)   // weights start offset in d_out (value first, weights second)

// Scratch (device globals — no allocation allowed)
__device__ float g_aproj[BB*HH*NN*F1D];   // av_act @ W_f1_h
__device__ float g_dproj[BB*HH*NN*F1D];   // (av_pol-av_act) @ W_f1_h
__device__ float g_M [HH*DMD*DMD];        // (W_q W_k^T) / sqrt(DM) per head
__device__ float g_v2[HH*DMD];            // (W_k b_q) / sqrt(DM) per head

__device__ __forceinline__ float lrelu(float x) { return x > 0.f ? x : 0.01f * x; }

#define INV_SQRT_DM 0.08838834764831845f

// ---------------------------------------------------------------------------
// k0: M_h = (W_q W_k^T)/sqrt(DM), v2_h = (W_k b_q)/sqrt(DM).
// grid = 256: h = bx>>6; rt = (bx>>2)&15 (8 d-rows); ct = bx&3 (32 d'-cols).
// ---------------------------------------------------------------------------
#define K0_SMEM_F (128 * 33)

__global__ __launch_bounds__(256)
void k0_prep(const float* __restrict__ W_q, const float* __restrict__ W_k,
             const float* __restrict__ b_q)
{
    const int h  = blockIdx.x >> 6;
    const int rt = (blockIdx.x >> 2) & 15;
    const int ct = blockIdx.x & 3;
    extern __shared__ float sm[];
    float* BT = sm;   // [128][33]: BT[e][dl] = W_k[h][ct*32+dl][e]
    const int tid  = threadIdx.x;
    const int w    = tid >> 5;
    const int lane = tid & 31;

    {
        const float* src = W_k + (size_t)h * DMD * DMD + (size_t)ct * 32 * DMD;
        for (int i = tid; i < 32 * DMD; i += 256) {
            int dl = i >> 7, e = i & 127;
            BT[e * 33 + dl] = src[i];
        }
    }
    __syncthreads();

    const int d = rt * 8 + w;
    const float4* Arow = (const float4*)(W_q + (size_t)h * DMD * DMD + (size_t)d * DMD);

    float a0 = 0.f, a1 = 0.f, a2 = 0.f, a3 = 0.f;
    #pragma unroll 8
    for (int e4 = 0; e4 < 32; e4++) {
        float4 a = __ldg(Arow + e4);                 // warp-uniform broadcast
        int eb = e4 * 4;
        a0 += a.x * BT[(eb + 0) * 33 + lane];
        a1 += a.y * BT[(eb + 1) * 33 + lane];
        a2 += a.z * BT[(eb + 2) * 33 + lane];
        a3 += a.w * BT[(eb + 3) * 33 + lane];
    }
    g_M[(size_t)h * DMD * DMD + (size_t)d * DMD + ct * 32 + lane] =
        ((a0 + a1) + (a2 + a3)) * INV_SQRT_DM;

    if (rt == 0 && w == 0) {
        const float* bq = b_q + h * DMD;
        float s0 = 0.f, s1 = 0.f, s2 = 0.f, s3 = 0.f;
        #pragma unroll 8
        for (int e = 0; e < DMD; e += 4) {
            s0 += BT[(e + 0) * 33 + lane] * __ldg(bq + e + 0);
            s1 += BT[(e + 1) * 33 + lane] * __ldg(bq + e + 1);
            s2 += BT[(e + 2) * 33 + lane] * __ldg(bq + e + 2);
            s3 += BT[(e + 3) * 33 + lane] * __ldg(bq + e + 3);
        }
        g_v2[h * DMD + ct * 32 + lane] = ((s0 + s1) + (s2 + s3)) * INV_SQRT_DM;
    }
}

// ---------------------------------------------------------------------------
// k12: merged attention (role 0) + state-action-pair (role 1) kernel.
// Exact Round-4 measured-good configuration: 3 CTAs/SM, 18720-float smem.
// ---------------------------------------------------------------------------
#define K12_SMEM_F (18720)

__global__ __launch_bounds__(256, 3)
void k12(const float* __restrict__ states,
         const float* __restrict__ policies,
         const float* __restrict__ actions,
         const float* __restrict__ W_se, const float* __restrict__ b_se,
         const float* __restrict__ W_sap, const float* __restrict__ b_sap,
         const float* __restrict__ W_av,  const float* __restrict__ b_av,
         const float* __restrict__ W_f1,
         float* __restrict__ out_w)
{
    extern __shared__ float sm[];
    const int tid  = threadIdx.x;
    const int role = blockIdx.x & 1;
    const int idx  = blockIdx.x >> 1;       // 0..511
    const int h    = idx & 3;
    const int b    = idx >> 2;

    if (role == 0) {
        // ================= attention weights =================
        float* sT  = sm;            // [128][36]  states o-major
        float* seT = sm + 4608;     // [128][36]  se d-major
        float* seR = sm + 9216;     // [32][132]  se row-major
        float* tb  = sm + 13440;    // [32][132]  t = se@M row-major
        float* sc  = sm + 17664;    // [32][32]
        float* rv  = sm + 18688;    // [32]

        const float* sb = states + b * NN * OBSD;
        for (int i = tid; i < NN * OBSD; i += 256) {
            int n = i >> 7, o = i & 127;
            sT[o * 36 + n] = sb[i];
        }
        __syncthreads();

        const int tr = tid >> 5;   // rows 4*tr
        const int tc = tid & 31;   // cols 4*tc

        // ---- se = leaky(states @ W_se + b_se) -> seT (d-major) + seR (row) ----
        {
            const float* Wh = W_se + (size_t)h * OBSD * DMD;
            float acc[4][4];
            #pragma unroll
            for (int r = 0; r < 4; r++)
                #pragma unroll
                for (int c = 0; c < 4; c++) acc[r][c] = 0.f;
            #pragma unroll 4
            for (int o = 0; o < OBSD; o++) {
                float4 a = *(const float4*)(sT + o * 36 + 4 * tr);
                float4 w = __ldg((const float4*)(Wh + o * DMD + 4 * tc));
                float av[4] = {a.x, a.y, a.z, a.w};
                float wv[4] = {w.x, w.y, w.z, w.w};
                #pragma unroll
                for (int r = 0; r < 4; r++)
                    #pragma unroll
                    for (int c = 0; c < 4; c++) acc[r][c] += av[r] * wv[c];
            }
            float4 bs = __ldg((const float4*)(b_se + h * DMD + 4 * tc));
            float bb4[4] = {bs.x, bs.y, bs.z, bs.w};
            #pragma unroll
            for (int c = 0; c < 4; c++) {
                int d = 4 * tc + c;
                #pragma unroll
                for (int r = 0; r < 4; r++) {
                    float v = lrelu(acc[r][c] + bb4[c]);
                    seT[d * 36 + 4 * tr + r] = v;
                    seR[(4 * tr + r) * 132 + d] = v;
                }
            }
        }
        __syncthreads();

        // ---- t = se @ M_h (pre-scaled) ----
        {
            const float* Mh = g_M + (size_t)h * DMD * DMD;
            float acc[4][4];
            #pragma unroll
            for (int r = 0; r < 4; r++)
                #pragma unroll
                for (int c = 0; c < 4; c++) acc[r][c] = 0.f;
            #pragma unroll 4
            for (int d = 0; d < DMD; d++) {
                float4 a = *(const float4*)(seT + d * 36 + 4 * tr);
                float4 w = __ldg((const float4*)(Mh + (size_t)d * DMD + 4 * tc));
                float av[4] = {a.x, a.y, a.z, a.w};
                float wv[4] = {w.x, w.y, w.z, w.w};
                #pragma unroll
                for (int r = 0; r < 4; r++)
                    #pragma unroll
                    for (int c = 0; c < 4; c++) acc[r][c] += av[r] * wv[c];
            }
            #pragma unroll
            for (int r = 0; r < 4; r++)
                *(float4*)(tb + (4 * tr + r) * 132 + 4 * tc) =
                    make_float4(acc[r][0], acc[r][1], acc[r][2], acc[r][3]);
        }
        // ---- rv[j] = v2 . se_j (threads 0..127) ----
        if (tid < 128) {
            const int j = tid >> 2, part = tid & 3;
            const float* v2 = g_v2 + h * DMD;
            float s = 0.f;
            #pragma unroll 8
            for (int e = part * 32; e < part * 32 + 32; e++)
                s += v2[e] * seR[j * 132 + e];
            s += __shfl_xor_sync(0xffffffffu, s, 1);
            s += __shfl_xor_sync(0xffffffffu, s, 2);
            if (part == 0) rv[j] = s;
        }
        __syncthreads();

        // ---- scores_ij = t_i . se_j + rv_j (already scaled) ----
        {
            const int i  = tid >> 3;
            const int j0 = (tid & 7) * 4;
            float s4[4] = {0.f, 0.f, 0.f, 0.f};
            #pragma unroll 4
            for (int e = 0; e < DMD; e += 4) {
                float4 qv = *(const float4*)(tb + i * 132 + e);
                #pragma unroll
                for (int jj = 0; jj < 4; jj++) {
                    float4 kv = *(const float4*)(seR + (j0 + jj) * 132 + e);
                    s4[jj] += qv.x * kv.x + qv.y * kv.y + qv.z * kv.z + qv.w * kv.w;
                }
            }
            #pragma unroll
            for (int jj = 0; jj < 4; jj++)
                sc[i * 32 + j0 + jj] = s4[jj] + rv[j0 + jj];
        }
        __syncthreads();

        // ---- softmax over j -> d_out tail ----
        {
            const int lane = tid & 31, wp = tid >> 5;
            float* dst = out_w + ((size_t)(b * HH + h) * NN) * NN;
            #pragma unroll
            for (int rr = 0; rr < 4; rr++) {
                int i = wp * 4 + rr;
                float v = sc[i * 32 + lane];
                float m = v;
                #pragma unroll
                for (int off = 16; off > 0; off >>= 1)
                    m = fmaxf(m, __shfl_xor_sync(0xffffffffu, m, off));
                float e = __expf(v - m);
                float s = e;
                #pragma unroll
                for (int off = 16; off > 0; off >>= 1)
                    s += __shfl_xor_sync(0xffffffffu, s, off);
                dst[i * NN + lane] = e / s;
            }
        }
    } else {
        // ================= sap embeddings -> Aproj/Dproj =================
        float* sT   = sm;            // [128][36]
        float* aT   = sm + 4608;     // [16][36]
        float* pT   = sm + 5184;     // [16][36]
        float* embT = sm + 5760;     // [128][68] cols 0..31 act, 32..63 pol
        float* avs  = sm;            // [64][36]  (aliases sT after emb phase)
        float* wf1h = sm + 5760;     // [32][64]  (aliases embT after av phase)

        const float* sb = states + b * NN * OBSD;
        for (int i = tid; i < NN * OBSD; i += 256) {
            int n = i >> 7, o = i & 127;
            sT[o * 36 + n] = sb[i];
        }
        const float* ab = actions  + b * NN * AD;
        const float* pb = policies + b * NN * AD;
        for (int i = tid; i < NN * AD; i += 256) {
            int n = i >> 4, c = i & 15;
            aT[c * 36 + n] = ab[i];
            pT[c * 36 + n] = pb[i];
        }
        __syncthreads();

        const int tr = tid >> 5;  // rows 4*tr of 32
        const int tc = tid & 31;  // cols 4*tc of 128

        // ---- sp = states @ W_sap[0:128]; emb = leaky(sp + tail + b) ----
        {
            const float* Wh = W_sap + (size_t)h * OAD * DMD;
            float acc[4][4];
            #pragma unroll
            for (int r = 0; r < 4; r++)
                #pragma unroll
                for (int c = 0; c < 4; c++) acc[r][c] = 0.f;
            #pragma unroll 4
            for (int o = 0; o < OBSD; o++) {
                float4 a = *(const float4*)(sT + o * 36 + 4 * tr);
                float4 w = __ldg((const float4*)(Wh + o * DMD + 4 * tc));
                float av[4] = {a.x, a.y, a.z, a.w};
                float wv[4] = {w.x, w.y, w.z, w.w};
                #pragma unroll
                for (int r = 0; r < 4; r++)
                    #pragma unroll
                    for (int c = 0; c < 4; c++) acc[r][c] += av[r] * wv[c];
            }
            float4 bs = __ldg((const float4*)(b_sap + h * DMD + 4 * tc));
            float bb4[4] = {bs.x, bs.y, bs.z, bs.w};

            // action tail + store
            {
                float accA[4][4];
                #pragma unroll
                for (int r = 0; r < 4; r++)
                    #pragma unroll
                    for (int c = 0; c < 4; c++) accA[r][c] = acc[r][c];
                #pragma unroll 4
                for (int c16 = 0; c16 < AD; c16++) {
                    float4 a = *(const float4*)(aT + c16 * 36 + 4 * tr);
                    float4 w = __ldg((const float4*)(Wh + (size_t)(OBSD + c16) * DMD + 4 * tc));
                    float av[4] = {a.x, a.y, a.z, a.w};
                    float wv[4] = {w.x, w.y, w.z, w.w};
                    #pragma unroll
                    for (int r = 0; r < 4; r++)
                        #pragma unroll
                        for (int c = 0; c < 4; c++) accA[r][c] += av[r] * wv[c];
                }
                #pragma unroll
                for (int c = 0; c < 4; c++) {
                    int d = 4 * tc + c;
                    #pragma unroll
                    for (int r = 0; r < 4; r++)
                        embT[d * 68 + 4 * tr + r] = lrelu(accA[r][c] + bb4[c]);
                }
            }
            // policy tail + store
            {
                float accP[4][4];
                #pragma unroll
                for (int r = 0; r < 4; r++)
                    #pragma unroll
                    for (int c = 0; c < 4; c++) accP[r][c] = acc[r][c];
                #pragma unroll 4
                for (int c16 = 0; c16 < AD; c16++) {
                    float4 a = *(const float4*)(pT + c16 * 36 + 4 * tr);
                    float4 w = __ldg((const float4*)(Wh + (size_t)(OBSD + c16) * DMD + 4 * tc));
                    float av[4] = {a.x, a.y, a.z, a.w};
                    float wv[4] = {w.x, w.y, w.z, w.w};
                    #pragma unroll
                    for (int r = 0; r < 4; r++)
                        #pragma unroll
                        for (int c = 0; c < 4; c++) accP[r][c] += av[r] * wv[c];
                }
                #pragma unroll
                for (int c = 0; c < 4; c++) {
                    int d = 4 * tc + c;
                    #pragma unroll
                    for (int r = 0; r < 4; r++)
                        embT[d * 68 + 32 + 4 * tr + r] = lrelu(accP[r][c] + bb4[c]);
                }
            }
        }
        __syncthreads();

        // ---- av (64 x 32) -> avs (aliases sT/aT/pT region; dead now) ----
        {
            const int tr2 = tid >> 4;  // 0..15 -> rows 4*tr2 of 64
            const int tc2 = tid & 15;  // 0..15 -> cols 2*tc2 of 32
            const float* Wh = W_av + (size_t)h * DMD * ED;
            float acc[4][2];
            #pragma unroll
            for (int r = 0; r < 4; r++) { acc[r][0] = 0.f; acc[r][1] = 0.f; }
            #pragma unroll 4
            for (int d = 0; d < DMD; d++) {
                float4 a = *(const float4*)(embT + d * 68 + 4 * tr2);
                float2 w = __ldg((const float2*)(Wh + d * ED + 2 * tc2));
                float av[4] = {a.x, a.y, a.z, a.w};
                #pragma unroll
                for (int r = 0; r < 4; r++) {
                    acc[r][0] += av[r] * w.x;
                    acc[r][1] += av[r] * w.y;
                }
            }
            float2 bv = __ldg((const float2*)(b_av + h * ED + 2 * tc2));
            #pragma unroll
            for (int r = 0; r < 4; r++) {
                int m = 4 * tr2 + r;
                avs[m * 36 + 2 * tc2]     = lrelu(acc[r][0] + bv.x);
                avs[m * 36 + 2 * tc2 + 1] = lrelu(acc[r][1] + bv.y);
            }
        }
        __syncthreads();   // embT reads done -> safe to overwrite with wf1h

        {
            const float4* src = (const float4*)(W_f1 + (size_t)h * ED * F1D);
            float4* dst = (float4*)wf1h;
            for (int i = tid; i < ED * F1D / 4; i += 256) dst[i] = src[i];
        }
        __syncthreads();

        // ---- Aproj / Dproj: [32][64] each ----
        {
            const int u  = tid & 63;
            const int i0 = tid >> 6;
            #pragma unroll
            for (int r = 0; r < 8; r++) {
                int j = i0 * 8 + r;
                float pa = 0.f, pd = 0.f;
                #pragma unroll 4
                for (int e = 0; e < ED; e++) {
                    float aa = avs[j * 36 + e];
                    float dd = avs[(32 + j) * 36 + e] - aa;
                    float wv = wf1h[e * F1D + u];
                    pa += aa * wv;
                    pd += dd * wv;
                }
                size_t o = ((size_t)(b * HH + h) * NN + j) * F1D + u;
                g_aproj[o] = pa;
                g_dproj[o] = pd;
            }
        }
    }
}

// ---------------------------------------------------------------------------
// K3: grid = 2*B; block (b, half) handles i-rows [half*16, half*16+16).
// ---------------------------------------------------------------------------
#define K3_SMEM_F (2048 + 8192 + 8448 + 1024 + 1024 + 64 + 16)

__global__ __launch_bounds__(256, 2)
void k3_final(const float* __restrict__ b_f1,
              const float* __restrict__ W_f2, const float* __restrict__ b_f2,
              const float* __restrict__ wgt,  // d_out + V0
              float* __restrict__ val)        // d_out
{
    const int half   = blockIdx.x & 1;
    const int b      = blockIdx.x >> 1;
    const int base_i = half * 16;
    extern __shared__ float sm[];
    float* w4h   = sm;           // [4][16][32]
    float* aproj = sm + 2048;    // [4][32][64]
    float* dpT   = sm + 10240;   // [4][64][33]
    float* P     = sm + 18688;   // [16][64]
    float* wf2   = sm + 19712;   // [64][16]
    float* bf1   = sm + 20736;   // [64]
    float* bf2   = sm + 20800;   // [16]
    const int tid = threadIdx.x;

    {
        const float* wg = wgt + (size_t)b * 4096;
        for (int i = tid; i < 2048 / 4; i += 256) {
            int e4 = i * 4;
            int hh = e4 >> 9, rem = e4 & 511;
            int il = rem >> 5, k = rem & 31;
            *(float4*)(w4h + e4) =
                *(const float4*)(wg + ((size_t)hh * 32 + base_i + il) * 32 + k);
        }
    }
    {
        const float4* src = (const float4*)(g_aproj + (size_t)b * 8192);
        float4* dst = (float4*)aproj;
        for (int i = tid; i < 2048; i += 256) dst[i] = src[i];
    }
    {
        const float* dp = g_dproj + (size_t)b * 8192;
        for (int i = tid; i < 8192; i += 256) {
            int hh = i >> 11, j = (i >> 6) & 31, u = i & 63;
            dpT[(hh * 64 + u) * 33 + j] = dp[i];
        }
    }
    for (int i = tid; i < 1024; i += 256) wf2[i] = W_f2[i];
    if (tid < 64) bf1[tid] = b_f1[tid];
    if (tid < 16) bf2[tid] = b_f2[tid];
    __syncthreads();

    // ---- P[il][u] ----
    {
        const int u  = tid & 63;
        const int i0 = tid >> 6;
        float pacc[4];
        #pragma unroll
        for (int r = 0; r < 4; r++) pacc[r] = bf1[u];
        #pragma unroll 2
        for (int hk = 0; hk < 128; hk++) {
            int hh = hk >> 5, k = hk & 31;
            float av = aproj[(hh * 32 + k) * 64 + u];
            #pragma unroll
            for (int r = 0; r < 4; r++)
                pacc[r] += w4h[hh * 512 + (i0 * 4 + r) * 32 + k] * av;
        }
        #pragma unroll
        for (int r = 0; r < 4; r++) P[(i0 * 4 + r) * 64 + u] = pacc[r];
    }
    __syncthreads();

    // ---- fused per-(i,j) MLP ----
    #pragma unroll
    for (int it = 0; it < 2; it++) {
        const int p  = tid + 256 * it;
        const int il = p >> 5;
        const int j  = p & 31;
        float wr0 = w4h[0 * 512 + il * 32 + j];
        float wr1 = w4h[1 * 512 + il * 32 + j];
        float wr2 = w4h[2 * 512 + il * 32 + j];
        float wr3 = w4h[3 * 512 + il * 32 + j];
        float o[16];
        #pragma unroll
        for (int f = 0; f < 16; f++) o[f] = bf2[f];
        #pragma unroll 8
        for (int u = 0; u < 64; u++) {
            float t = P[il * 64 + u];
            t += wr0 * dpT[(0 * 64 + u) * 33 + j];
            t += wr1 * dpT[(1 * 64 + u) * 33 + j];
            t += wr2 * dpT[(2 * 64 + u) * 33 + j];
            t += wr3 * dpT[(3 * 64 + u) * 33 + j];
            float hv = lrelu(t);
            float4 a  = *(const float4*)(wf2 + u * 16 + 0);
            float4 c4 = *(const float4*)(wf2 + u * 16 + 4);
            float4 c8 = *(const float4*)(wf2 + u * 16 + 8);
            float4 cc = *(const float4*)(wf2 + u * 16 + 12);
            o[0]  += hv * a.x;  o[1]  += hv * a.y;  o[2]  += hv * a.z;  o[3]  += hv * a.w;
            o[4]  += hv * c4.x; o[5]  += hv * c4.y; o[6]  += hv * c4.z; o[7]  += hv * c4.w;
            o[8]  += hv * c8.x; o[9]  += hv * c8.y; o[10] += hv * c8.z; o[11] += hv * c8.w;
            o[12] += hv * cc.x; o[13] += hv * cc.y; o[14] += hv * cc.z; o[15] += hv * cc.w;
        }
        float* dst = val + (((size_t)b * NN + base_i + il) * NN + j) * FIND;
        *(float4*)(dst + 0)  = make_float4(o[0],  o[1],  o[2],  o[3]);
        *(float4*)(dst + 4)  = make_float4(o[4],  o[5],  o[6],  o[7]);
        *(float4*)(dst + 8)  = make_float4(o[8],  o[9],  o[10], o[11]);
        *(float4*)(dst + 12) = make_float4(o[12], o[13], o[14], o[15]);
    }
}

// ---------------------------------------------------------------------------
extern "C" void kernel_launch(void* const* d_in, const int* in_sizes, int n_in,
                              void* d_out, int out_size)
{
    (void)in_sizes; (void)n_in; (void)out_size;
    const float* states   = (const float*)d_in[0];
    const float* policies = (const float*)d_in[1];
    const float* actions  = (const float*)d_in[2];
    const float* W_se  = (const float*)d_in[3];  const float* b_se = (const float*)d_in[4];
    const float* W_k   = (const float*)d_in[5];  const float* b_k  = (const float*)d_in[6];
    const float* W_q   = (const float*)d_in[7];  const float* b_q  = (const float*)d_in[8];
    const float* W_sap = (const float*)d_in[9];  const float* b_sap= (const float*)d_in[10];
    const float* W_av  = (const float*)d_in[11]; const float* b_av = (const float*)d_in[12];
    const float* W_f1  = (const float*)d_in[13]; const float* b_f1 = (const float*)d_in[14];
    const float* W_f2  = (const float*)d_in[15]; const float* b_f2 = (const float*)d_in[16];
    (void)b_k;
    float* out   = (float*)d_out;
    float* out_w = out + V0;

    cudaFuncSetAttribute(k0_prep,  cudaFuncAttributeMaxDynamicSharedMemorySize, K0_SMEM_F * 4);
    cudaFuncSetAttribute(k12,      cudaFuncAttributeMaxDynamicSharedMemorySize, K12_SMEM_F * 4);
    cudaFuncSetAttribute(k3_final, cudaFuncAttributeMaxDynamicSharedMemorySize, K3_SMEM_F * 4);

    k0_prep<<<256, 256, K0_SMEM_F * 4>>>(W_q, W_k, b_q);
    k12<<<BB * HH * 2, 256, K12_SMEM_F * 4>>>(states, policies, actions,
                                              W_se, b_se,
                                              W_sap, b_sap, W_av, b_av, W_f1, out_w);
    k3_final<<<BB * 2, 256, K3_SMEM_F * 4>>>(b_f1, W_f2, b_f2, out_w, out);
}